// round 13
// baseline (speedup 1.0000x reference)
#include <cuda_runtime.h>
#include <cstdint>

#define HH 56
#define WW 56
#define HM 50
#define WM 50
#define NPLANES 16384            // 64 * 256
#define COUNT_M 51380224ull      // 64*256*56*56
#define NSLOTS 512

// Scratch (allocation-free). g_partial is zero at load; k_finalize resets it
// after reading, so every graph replay sees zeros again.
__device__ unsigned g_partial[NSLOTS];
__device__ float g_scale;
__device__ unsigned long long g_dmask[NPLANES * HH];   // 7.34 MB packed dilated mask

// One CTA (128 thr) per plane. Front-batched streaming loads (MLP=5); all 20
// compares packed into one 20-bit mask -> a SINGLE rare-branch region holds
// every shift/atomic; (r,c) per chunk precomputed under load latency.
// Separable 7x7 bit dilation (OR of shifts 0..6 == window [o-6,o], matching
// the pad=6 reduce_window).
__global__ __launch_bounds__(128) void k_pass1(const float* __restrict__ u,
                                               const float* __restrict__ gamma) {
    __shared__ unsigned long long row[HM];   // seed mask, then dilated in place
    __shared__ unsigned wsum[2];
    const int plane = blockIdx.x;
    const int tid = threadIdx.x;
    const float g = __ldg(gamma);

    if (tid < HM) row[tid] = 0ull;

    // 625 float4 per plane; 5 batched loads per thread, 5th fed +inf when OOB
    // (inf < g is always false, so its nibble is 0 -> no predicate in the loop).
    const float4* u4 = (const float4*)(u + (size_t)plane * (HM * WM));
    float4 v[5];
    #pragma unroll
    for (int k = 0; k < 4; ++k) v[k] = __ldcs(u4 + tid + k * 128);
    const float finf = __int_as_float(0x7f800000);
    v[4] = make_float4(finf, finf, finf, finf);
    if (tid < 625 - 512) v[4] = __ldcs(u4 + tid + 512);

    // Precompute (row, col) per chunk — independent of loads, fills the wait.
    int rr[5], cc[5];
    #pragma unroll
    for (int k = 0; k < 5; ++k) {
        const int e = (tid + k * 128) * 4;
        rr[k] = e / WM;
        cc[k] = e - rr[k] * WM;
    }
    __syncthreads();   // row[] zeroed (placed after loads to overlap)

    unsigned bits = 0;
    #pragma unroll
    for (int k = 0; k < 5; ++k) {
        bits |= ( (unsigned)(v[k].x < g)
                | ((unsigned)(v[k].y < g) << 1)
                | ((unsigned)(v[k].z < g) << 2)
                | ((unsigned)(v[k].w < g) << 3) ) << (k * 4);
    }
    if (bits) {                                    // one branch region, rare per lane
        #pragma unroll
        for (int k = 0; k < 5; ++k) {
            const unsigned nib = (bits >> (k * 4)) & 0xFu;
            if (nib) {
                const unsigned long long m = (unsigned long long)nib << cc[k];
                const unsigned long long lo = m & ((1ull << WM) - 1ull);
                const unsigned long long hi = m >> WM;
                if (lo) atomicOr(&row[rr[k]], lo);
                if (hi) atomicOr(&row[rr[k] + 1], hi);   // cc in {47,48,49}; rr+1<=49
            }
        }
    }
    __syncthreads();

    // Horizontal dilation, in place (rows independent).
    if (tid < HM) {
        unsigned long long m  = row[tid];
        unsigned long long t1 = m  | (m  << 1);
        unsigned long long t2 = t1 | (t1 << 2);
        row[tid] = t2 | (t2 << 3);                 // shifts 0..6, bits stay < 56
    }
    __syncthreads();

    // Vertical dilation: output row o = OR of row[max(0,o-6) .. min(o,49)]
    unsigned v1 = 0;
    if (tid < HH) {
        int lo = tid - 6; if (lo < 0) lo = 0;
        int hi = (tid < HM) ? tid : (HM - 1);
        unsigned long long d = 0ull;
        #pragma unroll 1
        for (int r = lo; r <= hi; ++r) d |= row[r];
        g_dmask[(size_t)plane * HH + tid] = d;
        v1 = (unsigned)__popcll(d);
    }
    if (tid < 64) {
        #pragma unroll
        for (int off = 16; off; off >>= 1) v1 += __shfl_down_sync(0xffffffffu, v1, off);
        if ((tid & 31) == 0) wsum[tid >> 5] = v1;
    }
    __syncthreads();
    if (tid == 0)
        atomicAdd(&g_partial[plane & (NSLOTS - 1)], wsum[0] + wsum[1]);  // spread slots
}

// One block: sum the 512 slots, compute scale (f32, like the jnp reference),
// reset slots for the next replay.
__global__ __launch_bounds__(NSLOTS) void k_finalize() {
    __shared__ unsigned s[NSLOTS / 32];
    const int tid = threadIdx.x;
    unsigned v = g_partial[tid];
    g_partial[tid] = 0u;
    #pragma unroll
    for (int off = 16; off; off >>= 1) v += __shfl_down_sync(0xffffffffu, v, off);
    if ((tid & 31) == 0) s[tid >> 5] = v;
    __syncthreads();
    if (tid < 32) {
        unsigned w = (tid < NSLOTS / 32) ? s[tid] : 0u;
        #pragma unroll
        for (int off = 8; off; off >>= 1) w += __shfl_down_sync(0xffffffffu, w, off);
        if (tid == 0)
            g_scale = (float)COUNT_M / (float)(COUNT_M - (unsigned long long)w);
    }
}

// Elementwise apply, 4x float4 per thread, streaming loads/stores.
__global__ __launch_bounds__(256) void k_pass2(const float* __restrict__ x,
                                               float* __restrict__ out) {
    const unsigned base = blockIdx.x * 1024u + threadIdx.x;
    const float s = g_scale;

    unsigned i4[4], w4[4];
    unsigned long long d[4];
    float4 xv[4];
    #pragma unroll
    for (int j = 0; j < 4; ++j) {
        i4[j] = base + j * 256u;
        const unsigned p  = i4[j] / 784u;             // 784 float4 per 56x56 plane
        const unsigned rq = i4[j] - p * 784u;
        const unsigned row = rq / 14u;                // 14 float4 per row
        w4[j] = rq - row * 14u;
        d[j] = __ldg(&g_dmask[p * HH + row]);
        xv[j] = __ldcs(((const float4*)x) + i4[j]);
    }
    #pragma unroll
    for (int j = 0; j < 4; ++j) {
        const unsigned nib = (unsigned)(d[j] >> (w4[j] * 4u)) & 0xFu;
        float4 o;
        o.x = (nib & 1u) ? 0.f : xv[j].x * s;
        o.y = (nib & 2u) ? 0.f : xv[j].y * s;
        o.z = (nib & 4u) ? 0.f : xv[j].z * s;
        o.w = (nib & 8u) ? 0.f : xv[j].w * s;
        __stcs(((float4*)out) + i4[j], o);
    }
}

extern "C" void kernel_launch(void* const* d_in, const int* in_sizes, int n_in,
                              void* d_out, int out_size) {
    const float* x     = (const float*)d_in[0];
    const float* u     = (const float*)d_in[1];
    const float* gamma = (const float*)d_in[2];
    float* out = (float*)d_out;

    k_pass1<<<NPLANES, 128>>>(u, gamma);
    k_finalize<<<1, NSLOTS>>>();
    k_pass2<<<(unsigned)(COUNT_M / 4ull / 1024ull), 256>>>(x, out);   // 12544 blocks
}